// round 1
// baseline (speedup 1.0000x reference)
#include <cuda_runtime.h>
#include <cstdint>

#define B_ 32
#define L_ 2048
#define C_ 64
#define O_ 64
#define S_ 8
#define KS_ 9
#define HALO 8
#define OUT_ROWS ((L_ - 1) * (S_ + 1) + 1)   // 18424
#define TILE_L 64

// Scratch (no cudaMalloc allowed): P = F@W^T, Q = F@bias, each (B*L, 64) fp32.
__device__ float g_P[(size_t)B_ * L_ * O_];
__device__ float g_Q[(size_t)B_ * L_ * O_];
__device__ int g_mask_kind;

// non_pad_mask dtype probe. lengths >= L/2, so mask[0,0] and mask[0,1] are true.
// u8 layout:   bytes [1,1,...]       -> b0=1, b1=1
// i32 layout:  bytes [1,0,0,0,...]   -> b0=1, b1=0
// f32 layout:  bytes [0,0,0x80,0x3f] -> b0=0
__global__ void detect_mask_kind_kernel(const unsigned char* m) {
    unsigned char b0 = m[0], b1 = m[1];
    int k;
    if (b0 == 1 && b1 != 0) k = 0;       // uint8 / bool
    else if (b0 == 1)       k = 1;       // int32
    else                    k = 2;       // float32
    g_mask_kind = k;
}

// Kernel 1: P[r,o] = sum_c F[r,c]*W[o,c];  Q[r,o] = sum_c F[r,c]*bias[c,o]
// 64 rows per block, 256 threads, each thread: one o, 16 rows.
__global__ __launch_bounds__(256) void gemm_kernel(const float* __restrict__ F,
                                                   const float* __restrict__ W,
                                                   const float* __restrict__ bias) {
    __shared__ float Wt[64 * 64];   // transposed: Wt[c*64+o] = W[o*64+c]
    __shared__ float Bs[64 * 64];   // bias[c*64+o] as-is
    __shared__ float Fs[64 * 64];   // 64 rows of F
    int tid = threadIdx.x;
    size_t rowBase = (size_t)blockIdx.x * 64;

    for (int i = tid; i < 4096; i += 256) {
        int o = i >> 6, c = i & 63;
        Wt[c * 64 + o] = W[i];
    }
    const float4* bias4 = (const float4*)bias;
    const float4* f4 = (const float4*)(F + rowBase * 64);
    for (int i = tid; i < 1024; i += 256) {
        ((float4*)Bs)[i] = bias4[i];
        ((float4*)Fs)[i] = f4[i];
    }
    __syncthreads();

    int o = tid & 63;
    int rsub = tid >> 6;   // 0..3
    float accP[16], accQ[16];
#pragma unroll
    for (int j = 0; j < 16; j++) { accP[j] = 0.f; accQ[j] = 0.f; }

#pragma unroll 4
    for (int c = 0; c < 64; c++) {
        float w  = Wt[c * 64 + o];
        float bb = Bs[c * 64 + o];
#pragma unroll
        for (int j = 0; j < 16; j++) {
            float f = Fs[(rsub + 4 * j) * 64 + c];   // broadcast across warp
            accP[j] = fmaf(f, w,  accP[j]);
            accQ[j] = fmaf(f, bb, accQ[j]);
        }
    }

#pragma unroll
    for (int j = 0; j < 16; j++) {
        size_t r = rowBase + rsub + 4 * j;
        g_P[r * 64 + o] = accP[j];
        g_Q[r * 64 + o] = accQ[j];
    }
}

// Kernel 2: windowed combination + expansion into the (B, 18424, 64) output.
// Block: one (b, 64-l tile). 256 threads: o4 = 4 consecutive o per thread, 16 l lanes.
__global__ __launch_bounds__(256) void combine_kernel(const float* __restrict__ times,
                                                      const void* __restrict__ maskp,
                                                      const float* __restrict__ usample,
                                                      float* __restrict__ out) {
    __shared__ float Ps[(TILE_L + HALO) * 64];
    __shared__ float Qs[(TILE_L + HALO) * 64];
    __shared__ float ts[TILE_L + HALO + 1];
    __shared__ unsigned char vs[TILE_L + HALO + 1];
    __shared__ float us[S_];

    int tid = threadIdx.x;
    int b = blockIdx.y;
    int tileStart = blockIdx.x * TILE_L;
    int kind = g_mask_kind;

    const float* gP = g_P + (size_t)b * L_ * 64;
    const float* gQ = g_Q + (size_t)b * L_ * 64;

    const int NF4 = (TILE_L + HALO) * 16;   // float4 count
    for (int i = tid; i < NF4; i += 256) {
        int rr = i >> 4;        // row within tile (0..71)
        int cc = i & 15;        // float4 within row
        int gl = tileStart - HALO + rr;
        float4 p = make_float4(0.f, 0.f, 0.f, 0.f), q = p;
        if (gl >= 0) {
            p = ((const float4*)(gP + (size_t)gl * 64))[cc];
            q = ((const float4*)(gQ + (size_t)gl * 64))[cc];
        }
        ((float4*)Ps)[i] = p;
        ((float4*)Qs)[i] = q;
    }
    if (tid < TILE_L + HALO + 1) {
        int gl = tileStart - HALO + tid;
        float t = 0.f;
        unsigned char v = 0;
        if (gl >= 0 && gl < L_) {
            int mi = b * L_ + gl;
            t = times[mi];
            bool mv;
            if (kind == 0)      mv = ((const unsigned char*)maskp)[mi] != 0;
            else if (kind == 1) mv = ((const int*)maskp)[mi] != 0;
            else                mv = ((const float*)maskp)[mi] != 0.f;
            v = mv ? 1 : 0;
        }
        ts[tid] = t;
        vs[tid] = v;
    }
    if (tid < S_) us[tid] = usample[tid];
    __syncthreads();

    int o4 = (tid & 15) * 4;
    int lsub0 = tid >> 4;

    for (int l_local = lsub0; l_local < TILE_L; l_local += 16) {
        int l = tileStart + l_local;
        float tl = ts[l_local + HALO];
        float ml = vs[l_local + HALO] ? 1.f : 0.f;

        float rx = 0, ry = 0, rz = 0, rw = 0;   // real (k=0..7)
        float sx = 0, sy = 0, sz = 0, sw = 0;   // sim base (k=1..8)
        float ux = 0, uy = 0, uz = 0, uw = 0;   // sum_lin (k=1..8)

#pragma unroll
        for (int k = 0; k < KS_; k++) {
            int si = l_local + k;
            float m = vs[si] ? ml : 0.f;
            float d = m * (tl - ts[si]);   // delta_k (0 when masked)
            const float4 p = *(const float4*)&Ps[si * 64 + o4];
            const float4 q = *(const float4*)&Qs[si * 64 + o4];
            float tx = fmaf(d, p.x, m * q.x);
            float ty = fmaf(d, p.y, m * q.y);
            float tz = fmaf(d, p.z, m * q.z);
            float tw = fmaf(d, p.w, m * q.w);
            if (k < KS_ - 1) { rx += tx; ry += ty; rz += tz; rw += tw; }
            if (k >= 1) {
                sx += tx; sy += ty; sz += tz; sw += tw;
                ux = fmaf(m, p.x, ux); uy = fmaf(m, p.y, uy);
                uz = fmaf(m, p.z, uz); uw = fmaf(m, p.w, uw);
            }
        }

        float* ob = out + ((size_t)b * OUT_ROWS + (size_t)l * 9) * 64 + o4;
        *(float4*)ob = make_float4(rx, ry, rz, rw);

        if (l < L_ - 1) {
            float udt = (ml != 0.f && vs[l_local + HALO + 1])
                            ? (ts[l_local + HALO + 1] - tl) : 0.f;
#pragma unroll
            for (int s = 0; s < S_; s++) {
                float f = udt * us[s];
                float4 v = make_float4(fmaf(f, ux, sx), fmaf(f, uy, sy),
                                       fmaf(f, uz, sz), fmaf(f, uw, sw));
                *(float4*)(ob + (s + 1) * 64) = v;
            }
        }
    }
}

extern "C" void kernel_launch(void* const* d_in, const int* in_sizes, int n_in,
                              void* d_out, int out_size) {
    const float* times    = (const float*)d_in[0];
    const float* features = (const float*)d_in[1];
    const void*  mask     = d_in[2];
    const float* usample  = (const float*)d_in[3];
    const float* W        = (const float*)d_in[4];
    const float* bias     = (const float*)d_in[5];
    float* out = (float*)d_out;

    detect_mask_kind_kernel<<<1, 1>>>((const unsigned char*)mask);
    gemm_kernel<<<(B_ * L_) / 64, 256>>>(features, W, bias);
    dim3 g2(L_ / TILE_L, B_);
    combine_kernel<<<g2, 256>>>(times, mask, usample, out);
}